// round 3
// baseline (speedup 1.0000x reference)
#include <cuda_runtime.h>

typedef unsigned long long ULL;

#define BB 256
#define TT 1024
#define FF 64
#define UU 128
#define G3 384   // 3*U
#define NQ 96    // G3/4 column quads

// ---------------- scratch buffers (no cudaMalloc allowed) ----------------
static __device__ float g_xw1[(size_t)BB * TT * G3];   // input proj layer1 [B,T,384]
static __device__ float g_seq1[(size_t)BB * TT * UU];  // layer1 hidden seq [B,T,128]
static __device__ float g_xw2[(size_t)BB * TT * G3];   // input proj layer2 [B,T,384]

// ---------------- helpers ----------------
__device__ __forceinline__ ULL fma2(ULL a, ULL b, ULL c) {
    ULL d;
    asm("fma.rn.f32x2 %0, %1, %2, %3;" : "=l"(d) : "l"(a), "l"(b), "l"(c));
    return d;
}
__device__ __forceinline__ ULL pack2(float lo, float hi) {
    ULL d;
    asm("mov.b64 %0, {%1, %2};" : "=l"(d) : "f"(lo), "f"(hi));
    return d;
}
__device__ __forceinline__ float4 add4(float4 a, float4 b) {
    return make_float4(a.x + b.x, a.y + b.y, a.z + b.z, a.w + b.w);
}
__device__ __forceinline__ float sigm(float x) {
    return 1.0f / (1.0f + __expf(-x));
}

// =====================================================================
// GEMM: out[M,384] = X[M,K] @ W[K,384] + bias,  K = 4*KC (64 or 128)
// 384 threads: (cq in [0,96)) x (kg in [0,4)); 4 rows per block.
// W resident in smem as float4 per (k, colquad). X rows pre-packed (v,v).
// =====================================================================
template <int KC>
__global__ void __launch_bounds__(384, 1) gemm_kernel(
    const float* __restrict__ X, const float* __restrict__ W,
    const float* __restrict__ bias, float* __restrict__ out, int nblk)
{
    constexpr int K = 4 * KC;
    extern __shared__ char smem[];
    ulonglong2* Ws2   = (ulonglong2*)smem;                   // [K*96] as 2x u64
    float4*     Wf4   = (float4*)smem;
    ulonglong2* part2 = (ulonglong2*)(smem + (size_t)K * 1536);
    float4*     partf = (float4*)(smem + (size_t)K * 1536);  // [16][96]
    ULL*        xp    = (ULL*)(smem + (size_t)K * 1536 + 24576);  // [4*K] packed (v,v)
    float2*     xpf   = (float2*)xp;

    const int t  = threadIdx.x;
    const int cq = t % 96;
    const int kg = t / 96;          // 0..3
    const int kbase = kg * KC;

    for (int i = t; i < K * 96; i += 384) Wf4[i] = ((const float4*)W)[i];
    float4 bq = ((const float4*)bias)[cq];
    ULL b01 = pack2(bq.x, bq.y), b23 = pack2(bq.z, bq.w);
    __syncthreads();

    for (int blk = blockIdx.x; blk < nblk; blk += gridDim.x) {
        const int row0 = blk * 4;
        // pack 4 rows of X: contiguous, coalesced
        for (int i = t; i < 4 * K; i += 384) {
            float v = X[(size_t)row0 * K + i];
            xpf[i] = make_float2(v, v);
        }
        __syncthreads();

        ULL a0[4], a1[4];
#pragma unroll
        for (int r = 0; r < 4; r++) {
            a0[r] = (kg == 0) ? b01 : 0ull;
            a1[r] = (kg == 0) ? b23 : 0ull;
        }
        const ulonglong2* Up = Ws2 + kbase * 96 + cq;
        const ULL* x0 = xp + kbase;
#pragma unroll
        for (int kk = 0; kk < KC; kk++) {
            ulonglong2 u = Up[kk * 96];
            ULL h;
            h = x0[kk];           a0[0] = fma2(u.x, h, a0[0]); a1[0] = fma2(u.y, h, a1[0]);
            h = x0[K + kk];       a0[1] = fma2(u.x, h, a0[1]); a1[1] = fma2(u.y, h, a1[1]);
            h = x0[2 * K + kk];   a0[2] = fma2(u.x, h, a0[2]); a1[2] = fma2(u.y, h, a1[2]);
            h = x0[3 * K + kk];   a0[3] = fma2(u.x, h, a0[3]); a1[3] = fma2(u.y, h, a1[3]);
        }
        ulonglong2* P = part2 + kg * 4 * 96 + cq;
#pragma unroll
        for (int r = 0; r < 4; r++) P[r * 96] = make_ulonglong2(a0[r], a1[r]);
        __syncthreads();

        // reduce over kg: thread (r = kg, cq)
        {
            float4 s = partf[kg * 96 + cq];               // kg2 = 0 chunk
#pragma unroll
            for (int kg2 = 1; kg2 < 4; kg2++)
                s = add4(s, partf[(kg2 * 4 + kg) * 96 + cq]);
            ((float4*)out)[(size_t)(row0 + kg) * 96 + cq] = s;
        }
        __syncthreads();
    }
}

// =====================================================================
// GRU scan: per CTA 4 batch rows. U (128x384 fp32) resident in smem.
// Per step: rec = h @ U (+rbias), gates fused, h updated in smem.
// xw (precomputed input projection) streamed from global, prefetched
// one matmul ahead so its latency is hidden.
// =====================================================================
__global__ void __launch_bounds__(384, 1) scan_kernel(
    const float4* __restrict__ xw,      // [B*T*96] float4
    const float* __restrict__ Urec,     // [128,384]
    const float* __restrict__ rbias,    // [384]  (recurrent bias b[1])
    float4* __restrict__ seqout,        // [B*T*32] float4 or null
    float4* __restrict__ hfin1,         // [B*32] float4
    float4* __restrict__ hfin2)         // optional second copy or null
{
    extern __shared__ char smem[];
    ulonglong2* Us2   = (ulonglong2*)smem;                 // 196608 B
    float4*     Uf4   = (float4*)smem;
    ulonglong2* part2 = (ulonglong2*)(smem + 196608);      // 24576 B
    float4*     partf = (float4*)(smem + 196608);
    float4*     xws   = (float4*)(smem + 196608 + 24576);  // 6144 B: [4][96]
    ULL*        hp    = (ULL*)(smem + 196608 + 24576 + 6144); // 4096 B: [4][128] packed (h,h)
    float2*     hpf2  = (float2*)hp;
    const float* hpf  = (const float*)hp;

    const int t  = threadIdx.x;
    const int cq = t % 96;
    const int kg = t / 96;          // 0..3
    const int kbase = kg * 32;
    const int row0 = blockIdx.x * 4;
    const int r_g = t >> 5;         // gate-phase row (t<128)
    const int gq  = t & 31;         // gate quad

    for (int i = t; i < 128 * 96; i += 384) Uf4[i] = ((const float4*)Urec)[i];
    for (int i = t; i < 512; i += 384) hp[i] = 0ull;
    float4 bq = ((const float4*)rbias)[cq];
    ULL b01 = pack2(bq.x, bq.y), b23 = pack2(bq.z, bq.w);
    __syncthreads();

    for (int step = 0; step < TT; ++step) {
        // prefetch this step's xw (consumed after the matmul -> latency hidden)
        float4 xv = xw[((size_t)(row0 + kg) * TT + step) * 96 + cq];

        ULL a0[4], a1[4];
#pragma unroll
        for (int r = 0; r < 4; r++) {
            a0[r] = (kg == 0) ? b01 : 0ull;
            a1[r] = (kg == 0) ? b23 : 0ull;
        }
        const ulonglong2* Up = Us2 + kbase * 96 + cq;
        const ULL* h0 = hp + kbase;
#pragma unroll
        for (int kk = 0; kk < 32; kk++) {
            ulonglong2 u = Up[kk * 96];
            ULL h;
            h = h0[kk];        a0[0] = fma2(u.x, h, a0[0]); a1[0] = fma2(u.y, h, a1[0]);
            h = h0[128 + kk];  a0[1] = fma2(u.x, h, a0[1]); a1[1] = fma2(u.y, h, a1[1]);
            h = h0[256 + kk];  a0[2] = fma2(u.x, h, a0[2]); a1[2] = fma2(u.y, h, a1[2]);
            h = h0[384 + kk];  a0[3] = fma2(u.x, h, a0[3]); a1[3] = fma2(u.y, h, a1[3]);
        }
        ulonglong2* P = part2 + kg * 4 * 96 + cq;
#pragma unroll
        for (int r = 0; r < 4; r++) P[r * 96] = make_ulonglong2(a0[r], a1[r]);
        xws[kg * 96 + cq] = xv;   // r == kg for the xw staging
        __syncthreads();

        if (t < 128) {
            // reduce 4 k-group partials for the gate triple (z, r, h)
            float4 az = partf[r_g * 96 + gq];
            float4 ar = partf[r_g * 96 + gq + 32];
            float4 ah = partf[r_g * 96 + gq + 64];
#pragma unroll
            for (int kg2 = 1; kg2 < 4; kg2++) {
                az = add4(az, partf[(kg2 * 4 + r_g) * 96 + gq]);
                ar = add4(ar, partf[(kg2 * 4 + r_g) * 96 + gq + 32]);
                ah = add4(ah, partf[(kg2 * 4 + r_g) * 96 + gq + 64]);
            }
            float4 xz = xws[r_g * 96 + gq];
            float4 xr = xws[r_g * 96 + gq + 32];
            float4 xh = xws[r_g * 96 + gq + 64];

            float azv[4] = {az.x, az.y, az.z, az.w};
            float arv[4] = {ar.x, ar.y, ar.z, ar.w};
            float ahv[4] = {ah.x, ah.y, ah.z, ah.w};
            float xzv[4] = {xz.x, xz.y, xz.z, xz.w};
            float xrv[4] = {xr.x, xr.y, xr.z, xr.w};
            float xhv[4] = {xh.x, xh.y, xh.z, xh.w};
            float hn[4];
            const int hb = r_g * 128 + 4 * gq;
#pragma unroll
            for (int e = 0; e < 4; e++) {
                float hold = hpf[2 * (hb + e)];
                float z  = sigm(xzv[e] + azv[e]);
                float rr = sigm(xrv[e] + arv[e]);
                float hh = fmaxf(xhv[e] + rr * ahv[e], 0.0f);
                hn[e] = z * hold + (1.0f - z) * hh;
                hpf2[hb + e] = make_float2(hn[e], hn[e]);
            }
            if (seqout)
                seqout[((size_t)(row0 + r_g) * TT + step) * 32 + gq] =
                    make_float4(hn[0], hn[1], hn[2], hn[3]);
        }
        __syncthreads();
    }

    if (t < 128) {
        const int hb = r_g * 128 + 4 * gq;
        float4 hv = make_float4(hpf[2 * hb], hpf[2 * (hb + 1)],
                                hpf[2 * (hb + 2)], hpf[2 * (hb + 3)]);
        hfin1[(size_t)(row0 + r_g) * 32 + gq] = hv;
        if (hfin2) hfin2[(size_t)(row0 + r_g) * 32 + gq] = hv;
    }
}

// =====================================================================
// launch
// =====================================================================
extern "C" void kernel_launch(void* const* d_in, const int* in_sizes, int n_in,
                              void* d_out, int out_size)
{
    (void)in_sizes; (void)n_in; (void)out_size;
    const float* input = (const float*)d_in[0];  // [256,1024,64]
    const float* W1    = (const float*)d_in[1];  // [64,384]
    const float* U1    = (const float*)d_in[2];  // [128,384]
    const float* b1    = (const float*)d_in[3];  // [2,384]
    const float* W2    = (const float*)d_in[4];  // [128,384]
    const float* U2    = (const float*)d_in[5];  // [128,384]
    const float* b2    = (const float*)d_in[6];  // [2,384]
    float* out = (float*)d_out;                  // [3*256*128]: x | state1 | state2

    float *xw1, *seq1, *xw2;
    cudaGetSymbolAddress((void**)&xw1,  g_xw1);
    cudaGetSymbolAddress((void**)&seq1, g_seq1);
    cudaGetSymbolAddress((void**)&xw2,  g_xw2);

    const int SMEM_G1 = 64 * 1536 + 24576 + 2048;    // 124928
    const int SMEM_G2 = 128 * 1536 + 24576 + 4096;   // 225280
    const int SMEM_S  = 196608 + 24576 + 6144 + 4096; // 231424

    cudaFuncSetAttribute(gemm_kernel<16>, cudaFuncAttributeMaxDynamicSharedMemorySize, SMEM_G1);
    cudaFuncSetAttribute(gemm_kernel<32>, cudaFuncAttributeMaxDynamicSharedMemorySize, SMEM_G2);
    cudaFuncSetAttribute(scan_kernel,     cudaFuncAttributeMaxDynamicSharedMemorySize, SMEM_S);

    const int nblk = (BB * TT) / 4;  // 65536 row-blocks of 4

    // Layer 1 input projection: xw1 = input @ W1 + b1[0]
    gemm_kernel<16><<<148, 384, SMEM_G1>>>(input, W1, b1, xw1, nblk);
    // Layer 1 scan: seq1, state1
    scan_kernel<<<64, 384, SMEM_S>>>((const float4*)xw1, U1, b1 + G3,
                                     (float4*)seq1,
                                     (float4*)(out + 32768), nullptr);
    // Layer 2 input projection: xw2 = seq1 @ W2 + b2[0]
    gemm_kernel<32><<<148, 384, SMEM_G2>>>(seq1, W2, b2, xw2, nblk);
    // Layer 2 scan: x (== state2)
    scan_kernel<<<64, 384, SMEM_S>>>((const float4*)xw2, U2, b2 + G3,
                                     nullptr,
                                     (float4*)out, (float4*)(out + 65536));
}

// round 4
// speedup vs baseline: 1.2800x; 1.2800x over previous
#include <cuda_runtime.h>

typedef unsigned long long ULL;

#define BB 256
#define TT 1024
#define FF 64
#define UU 128
#define G3 384   // 3*U

// ---------------- scratch buffers (no cudaMalloc allowed) ----------------
static __device__ float g_xw1[(size_t)BB * TT * G3];   // input proj layer1 [B,T,384]
static __device__ float g_seq1[(size_t)BB * TT * UU];  // layer1 hidden seq [B,T,128]
static __device__ float g_xw2[(size_t)BB * TT * G3];   // input proj layer2 [B,T,384]

// ---------------- helpers ----------------
__device__ __forceinline__ ULL fma2(ULL a, ULL b, ULL c) {
    ULL d;
    asm("fma.rn.f32x2 %0, %1, %2, %3;" : "=l"(d) : "l"(a), "l"(b), "l"(c));
    return d;
}
__device__ __forceinline__ ULL pack2(float lo, float hi) {
    ULL d;
    asm("mov.b64 %0, {%1, %2};" : "=l"(d) : "f"(lo), "f"(hi));
    return d;
}
__device__ __forceinline__ float4 add4(float4 a, float4 b) {
    return make_float4(a.x + b.x, a.y + b.y, a.z + b.z, a.w + b.w);
}
__device__ __forceinline__ float2 add2(float2 a, float2 b) {
    return make_float2(a.x + b.x, a.y + b.y);
}
__device__ __forceinline__ float sigm(float x) {
    return 1.0f / (1.0f + __expf(-x));
}

// =====================================================================
// GEMM: out[M,384] = X[M,K] @ W[K,384] + bias,  K = 4*KC (64 or 128)
// 384 threads: (cq in [0,96)) x (kg in [0,4)); 4 rows per block.
// (unchanged from R3 — ~550us combined, not the bottleneck yet)
// =====================================================================
template <int KC>
__global__ void __launch_bounds__(384, 1) gemm_kernel(
    const float* __restrict__ X, const float* __restrict__ W,
    const float* __restrict__ bias, float* __restrict__ out, int nblk)
{
    constexpr int K = 4 * KC;
    extern __shared__ char smem[];
    ulonglong2* Ws2   = (ulonglong2*)smem;
    float4*     Wf4   = (float4*)smem;
    ulonglong2* part2 = (ulonglong2*)(smem + (size_t)K * 1536);
    float4*     partf = (float4*)(smem + (size_t)K * 1536);
    ULL*        xp    = (ULL*)(smem + (size_t)K * 1536 + 24576);
    float2*     xpf   = (float2*)xp;

    const int t  = threadIdx.x;
    const int cq = t % 96;
    const int kg = t / 96;
    const int kbase = kg * KC;

    for (int i = t; i < K * 96; i += 384) Wf4[i] = ((const float4*)W)[i];
    float4 bq = ((const float4*)bias)[cq];
    ULL b01 = pack2(bq.x, bq.y), b23 = pack2(bq.z, bq.w);
    __syncthreads();

    for (int blk = blockIdx.x; blk < nblk; blk += gridDim.x) {
        const int row0 = blk * 4;
        for (int i = t; i < 4 * K; i += 384) {
            float v = X[(size_t)row0 * K + i];
            xpf[i] = make_float2(v, v);
        }
        __syncthreads();

        ULL a0[4], a1[4];
#pragma unroll
        for (int r = 0; r < 4; r++) {
            a0[r] = (kg == 0) ? b01 : 0ull;
            a1[r] = (kg == 0) ? b23 : 0ull;
        }
        const ulonglong2* Up = Ws2 + kbase * 96 + cq;
        const ULL* x0 = xp + kbase;
#pragma unroll
        for (int kk = 0; kk < KC; kk++) {
            ulonglong2 u = Up[kk * 96];
            ULL h;
            h = x0[kk];           a0[0] = fma2(u.x, h, a0[0]); a1[0] = fma2(u.y, h, a1[0]);
            h = x0[K + kk];       a0[1] = fma2(u.x, h, a0[1]); a1[1] = fma2(u.y, h, a1[1]);
            h = x0[2 * K + kk];   a0[2] = fma2(u.x, h, a0[2]); a1[2] = fma2(u.y, h, a1[2]);
            h = x0[3 * K + kk];   a0[3] = fma2(u.x, h, a0[3]); a1[3] = fma2(u.y, h, a1[3]);
        }
        ulonglong2* P = part2 + kg * 4 * 96 + cq;
#pragma unroll
        for (int r = 0; r < 4; r++) P[r * 96] = make_ulonglong2(a0[r], a1[r]);
        __syncthreads();

        {
            float4 s = partf[kg * 96 + cq];
#pragma unroll
            for (int kg2 = 1; kg2 < 4; kg2++)
                s = add4(s, partf[(kg2 * 4 + kg) * 96 + cq]);
            ((float4*)out)[(size_t)(row0 + kg) * 96 + cq] = s;
        }
        __syncthreads();
    }
}

// =====================================================================
// GRU scan v2: 128 CTAs x 2 batch rows, 768 threads (24 warps).
// U (128x384 fp32, 192KB) resident in smem. k split into 8 groups of 16.
// Per step: rec = h @ U (+rbias); partials in smem; 128-thread gate tail.
// =====================================================================
__global__ void __launch_bounds__(768, 1) scan_kernel(
    const float4* __restrict__ xw,      // [B*T*96] float4
    const float* __restrict__ Urec,     // [128,384]
    const float* __restrict__ rbias,    // [384]
    float2* __restrict__ seqout,        // [B*T*64] float2 or null
    float2* __restrict__ hfin1,         // [B*64] float2
    float2* __restrict__ hfin2)         // optional second copy or null
{
    extern __shared__ char smem[];
    ulonglong2*  Us2   = (ulonglong2*)smem;                   // 196608 B
    float4*      Uf4   = (float4*)smem;
    ulonglong2*  part2 = (ulonglong2*)(smem + 196608);        // 24576 B: [16][96]
    const float2* partf2 = (const float2*)(smem + 196608);
    float4*      xws   = (float4*)(smem + 196608 + 24576);    // 3072 B: [2][96]
    const float2* xwsf2 = (const float2*)(smem + 196608 + 24576);
    ULL*         hp    = (ULL*)(smem + 196608 + 24576 + 3072); // 2048 B: [2][128] packed (h,h)
    float2*      hpf2  = (float2*)hp;

    const int t  = threadIdx.x;
    const int cq = t % 96;
    const int kg = t / 96;          // 0..7
    const int kbase = kg * 16;
    const int row0 = blockIdx.x * 2;

    // gate-phase mapping (t < 128): 2 rows x 64 element-pairs
    const int r_g = t >> 6;         // 0..1
    const int p   = t & 63;         // pair index; elements 2p, 2p+1
    const int ph  = p >> 1;         // quad index within gate block
    const int pl  = p & 1;          // which float2 half of the quad

    for (int i = t; i < 128 * 96; i += 768) Uf4[i] = ((const float4*)Urec)[i];
    for (int i = t; i < 256; i += 768) hp[i] = 0ull;
    float4 bq = ((const float4*)rbias)[cq];
    ULL b01 = pack2(bq.x, bq.y), b23 = pack2(bq.z, bq.w);
    __syncthreads();

    const ulonglong2* Up = Us2 + kbase * 96 + cq;
    const ULL* h0 = hp + kbase;
    const ULL* h1 = hp + 128 + kbase;

    for (int step = 0; step < TT; ++step) {
        // prefetch this step's xw early (global, consumed after the matmul)
        float4 xv = make_float4(0.f, 0.f, 0.f, 0.f);
        if (t < 192)
            xv = xw[((size_t)(row0 + (t / 96)) * TT + step) * 96 + (t % 96)];

        ULL a0r0 = (kg == 0) ? b01 : 0ull, a1r0 = (kg == 0) ? b23 : 0ull;
        ULL a0r1 = a0r0, a1r1 = a1r0;
#pragma unroll
        for (int kk = 0; kk < 16; kk++) {
            ulonglong2 u = Up[kk * 96];
            ULL ha = h0[kk];
            ULL hb = h1[kk];
            a0r0 = fma2(u.x, ha, a0r0); a1r0 = fma2(u.y, ha, a1r0);
            a0r1 = fma2(u.x, hb, a0r1); a1r1 = fma2(u.y, hb, a1r1);
        }
        part2[(kg * 2 + 0) * 96 + cq] = make_ulonglong2(a0r0, a1r0);
        part2[(kg * 2 + 1) * 96 + cq] = make_ulonglong2(a0r1, a1r1);
        if (t < 192) xws[t] = xv;
        __syncthreads();

        if (t < 128) {
            // reduce 8 k-group partials for gates z,r,h at float2 granularity
            float2 az = partf2[(r_g * 96 + ph) * 2 + pl];
            float2 ar = partf2[(r_g * 96 + 32 + ph) * 2 + pl];
            float2 ah = partf2[(r_g * 96 + 64 + ph) * 2 + pl];
#pragma unroll
            for (int kg2 = 1; kg2 < 8; kg2++) {
                const int rb = (kg2 * 2 + r_g) * 96;
                az = add2(az, partf2[(rb + ph) * 2 + pl]);
                ar = add2(ar, partf2[(rb + 32 + ph) * 2 + pl]);
                ah = add2(ah, partf2[(rb + 64 + ph) * 2 + pl]);
            }
            float2 xz = xwsf2[(r_g * 96 + ph) * 2 + pl];
            float2 xr = xwsf2[(r_g * 96 + 32 + ph) * 2 + pl];
            float2 xh = xwsf2[(r_g * 96 + 64 + ph) * 2 + pl];

            const int hb = r_g * 128 + 2 * p;
            float hold0 = hpf2[hb].x;
            float hold1 = hpf2[hb + 1].x;

            float z0 = sigm(xz.x + az.x);
            float z1 = sigm(xz.y + az.y);
            float rr0 = sigm(xr.x + ar.x);
            float rr1 = sigm(xr.y + ar.y);
            float hh0 = fmaxf(xh.x + rr0 * ah.x, 0.0f);
            float hh1 = fmaxf(xh.y + rr1 * ah.y, 0.0f);
            float hn0 = z0 * hold0 + (1.0f - z0) * hh0;
            float hn1 = z1 * hold1 + (1.0f - z1) * hh1;
            hpf2[hb]     = make_float2(hn0, hn0);
            hpf2[hb + 1] = make_float2(hn1, hn1);

            if (seqout)
                seqout[((size_t)(row0 + r_g) * TT + step) * 64 + p] =
                    make_float2(hn0, hn1);
        }
        __syncthreads();
    }

    if (t < 128) {
        const int hb = r_g * 128 + 2 * p;
        float2 hv = make_float2(hpf2[hb].x, hpf2[hb + 1].x);
        hfin1[(size_t)(row0 + r_g) * 64 + p] = hv;
        if (hfin2) hfin2[(size_t)(row0 + r_g) * 64 + p] = hv;
    }
}

// =====================================================================
// launch
// =====================================================================
extern "C" void kernel_launch(void* const* d_in, const int* in_sizes, int n_in,
                              void* d_out, int out_size)
{
    (void)in_sizes; (void)n_in; (void)out_size;
    const float* input = (const float*)d_in[0];  // [256,1024,64]
    const float* W1    = (const float*)d_in[1];  // [64,384]
    const float* U1    = (const float*)d_in[2];  // [128,384]
    const float* b1    = (const float*)d_in[3];  // [2,384]
    const float* W2    = (const float*)d_in[4];  // [128,384]
    const float* U2    = (const float*)d_in[5];  // [128,384]
    const float* b2    = (const float*)d_in[6];  // [2,384]
    float* out = (float*)d_out;                  // [3*256*128]: x | state1 | state2

    float *xw1, *seq1, *xw2;
    cudaGetSymbolAddress((void**)&xw1,  g_xw1);
    cudaGetSymbolAddress((void**)&seq1, g_seq1);
    cudaGetSymbolAddress((void**)&xw2,  g_xw2);

    const int SMEM_G1 = 64 * 1536 + 24576 + 2048;           // 124928
    const int SMEM_G2 = 128 * 1536 + 24576 + 4096;          // 225280
    const int SMEM_S  = 196608 + 24576 + 3072 + 2048;       // 226304

    cudaFuncSetAttribute(gemm_kernel<16>, cudaFuncAttributeMaxDynamicSharedMemorySize, SMEM_G1);
    cudaFuncSetAttribute(gemm_kernel<32>, cudaFuncAttributeMaxDynamicSharedMemorySize, SMEM_G2);
    cudaFuncSetAttribute(scan_kernel,     cudaFuncAttributeMaxDynamicSharedMemorySize, SMEM_S);

    const int nblk = (BB * TT) / 4;  // 65536 row-blocks of 4

    // Layer 1 input projection: xw1 = input @ W1 + b1[0]
    gemm_kernel<16><<<148, 384, SMEM_G1>>>(input, W1, b1, xw1, nblk);
    // Layer 1 scan: seq1, state1
    scan_kernel<<<128, 768, SMEM_S>>>((const float4*)xw1, U1, b1 + G3,
                                      (float2*)seq1,
                                      (float2*)(out + 32768), nullptr);
    // Layer 2 input projection: xw2 = seq1 @ W2 + b2[0]
    gemm_kernel<32><<<148, 384, SMEM_G2>>>(seq1, W2, b2, xw2, nblk);
    // Layer 2 scan: x (== state2)
    scan_kernel<<<128, 768, SMEM_S>>>((const float4*)xw2, U2, b2 + G3,
                                      nullptr,
                                      (float2*)out, (float2*)(out + 65536));
}

// round 5
// speedup vs baseline: 1.3559x; 1.0593x over previous
#include <cuda_runtime.h>

typedef unsigned long long ULL;

#define BB 256
#define TT 1024
#define FF 64
#define UU 128
#define G3 384   // 3*U

// ---------------- scratch buffers (no cudaMalloc allowed) ----------------
static __device__ float g_xw1[(size_t)BB * TT * G3];   // input proj layer1 [B,T,384]
static __device__ float g_seq1[(size_t)BB * TT * UU];  // layer1 hidden seq [B,T,128]
static __device__ float g_xw2[(size_t)BB * TT * G3];   // input proj layer2 [B,T,384]

// ---------------- helpers ----------------
__device__ __forceinline__ ULL fma2(ULL a, ULL b, ULL c) {
    ULL d;
    asm("fma.rn.f32x2 %0, %1, %2, %3;" : "=l"(d) : "l"(a), "l"(b), "l"(c));
    return d;
}
__device__ __forceinline__ ULL addp(ULL a, ULL b) {
    ULL d;
    asm("add.rn.f32x2 %0, %1, %2;" : "=l"(d) : "l"(a), "l"(b));
    return d;
}
__device__ __forceinline__ ULL pack2(float lo, float hi) {
    ULL d;
    asm("mov.b64 %0, {%1, %2};" : "=l"(d) : "f"(lo), "f"(hi));
    return d;
}
__device__ __forceinline__ float2 unpack2(ULL v) {
    float lo, hi;
    asm("mov.b64 {%0, %1}, %2;" : "=f"(lo), "=f"(hi) : "l"(v));
    return make_float2(lo, hi);
}
__device__ __forceinline__ float4 add4(float4 a, float4 b) {
    return make_float4(a.x + b.x, a.y + b.y, a.z + b.z, a.w + b.w);
}
__device__ __forceinline__ float sigm(float x) {
    return 1.0f / (1.0f + __expf(-x));
}

// =====================================================================
// GEMM: out[M,384] = X[M,K] @ W[K,384] + bias,  K = 4*KC (64 or 128)
// (unchanged — ~500us combined; tensor-core rewrite is a later round)
// =====================================================================
template <int KC>
__global__ void __launch_bounds__(384, 1) gemm_kernel(
    const float* __restrict__ X, const float* __restrict__ W,
    const float* __restrict__ bias, float* __restrict__ out, int nblk)
{
    constexpr int K = 4 * KC;
    extern __shared__ char smem[];
    ulonglong2* Ws2   = (ulonglong2*)smem;
    float4*     Wf4   = (float4*)smem;
    ulonglong2* part2 = (ulonglong2*)(smem + (size_t)K * 1536);
    float4*     partf = (float4*)(smem + (size_t)K * 1536);
    ULL*        xp    = (ULL*)(smem + (size_t)K * 1536 + 24576);
    float2*     xpf   = (float2*)xp;

    const int t  = threadIdx.x;
    const int cq = t % 96;
    const int kg = t / 96;
    const int kbase = kg * KC;

    for (int i = t; i < K * 96; i += 384) Wf4[i] = ((const float4*)W)[i];
    float4 bq = ((const float4*)bias)[cq];
    ULL b01 = pack2(bq.x, bq.y), b23 = pack2(bq.z, bq.w);
    __syncthreads();

    for (int blk = blockIdx.x; blk < nblk; blk += gridDim.x) {
        const int row0 = blk * 4;
        for (int i = t; i < 4 * K; i += 384) {
            float v = X[(size_t)row0 * K + i];
            xpf[i] = make_float2(v, v);
        }
        __syncthreads();

        ULL a0[4], a1[4];
#pragma unroll
        for (int r = 0; r < 4; r++) {
            a0[r] = (kg == 0) ? b01 : 0ull;
            a1[r] = (kg == 0) ? b23 : 0ull;
        }
        const ulonglong2* Up = Ws2 + kbase * 96 + cq;
        const ULL* x0 = xp + kbase;
#pragma unroll
        for (int kk = 0; kk < KC; kk++) {
            ulonglong2 u = Up[kk * 96];
            ULL h;
            h = x0[kk];           a0[0] = fma2(u.x, h, a0[0]); a1[0] = fma2(u.y, h, a1[0]);
            h = x0[K + kk];       a0[1] = fma2(u.x, h, a0[1]); a1[1] = fma2(u.y, h, a1[1]);
            h = x0[2 * K + kk];   a0[2] = fma2(u.x, h, a0[2]); a1[2] = fma2(u.y, h, a1[2]);
            h = x0[3 * K + kk];   a0[3] = fma2(u.x, h, a0[3]); a1[3] = fma2(u.y, h, a1[3]);
        }
        ulonglong2* P = part2 + kg * 4 * 96 + cq;
#pragma unroll
        for (int r = 0; r < 4; r++) P[r * 96] = make_ulonglong2(a0[r], a1[r]);
        __syncthreads();

        {
            float4 s = partf[kg * 96 + cq];
#pragma unroll
            for (int kg2 = 1; kg2 < 4; kg2++)
                s = add4(s, partf[(kg2 * 4 + kg) * 96 + cq]);
            ((float4*)out)[(size_t)(row0 + kg) * 96 + cq] = s;
        }
        __syncthreads();
    }
}

// =====================================================================
// GRU scan v3: U register-resident. 128 CTAs x 2 rows, 256 threads.
// Thread (q in [0,64), kg = lane>>3): owns U[kg*32..+32, cols {2q,2q+1}
// of each gate z/r/h] = 96 packed-f32x2 regs. Per step:
//   mainloop: h broadcast from smem (double-buffered), 192 fma2 from regs
//   kg-reduction: shfl.bfly xor8 + xor16 (warp-local, no smem partials)
//   gates: computed in-thread (z/r/h triplet is thread-local), h_old in regs
//   one __syncthreads per step.
// =====================================================================
__global__ void __launch_bounds__(256, 1) scan_kernel(
    const float* __restrict__ xw,       // [B,T,384]
    const float* __restrict__ Urec,     // [128,384]
    const float* __restrict__ rbias,    // [384]
    float2* __restrict__ seqout,        // [B,T,64] float2 or null
    float2* __restrict__ hfin1,         // [B,64] float2
    float2* __restrict__ hfin2)         // optional second copy or null
{
    __shared__ alignas(16) ULL hp[2][2][UU];   // [buf][row][k] packed (h,h)

    const int t    = threadIdx.x;
    const int lane = t & 31;
    const int w    = t >> 5;
    const int q    = (w << 3) | (lane & 7);    // 0..63  output pair
    const int kg   = lane >> 3;                // 0..3   k-slice
    const int kbase = kg * 32;
    const int row0 = blockIdx.x * 2;

    // ---- load this thread's U slice into registers: Ur[kk][g] = (U[k][2cp], U[k][2cp+1])
    ULL Ur[32][3];
#pragma unroll
    for (int kk = 0; kk < 32; kk++) {
#pragma unroll
        for (int g = 0; g < 3; g++) {
            float2 u = *(const float2*)(Urec + (size_t)(kbase + kk) * G3 + g * 128 + 2 * q);
            Ur[kk][g] = pack2(u.x, u.y);
        }
    }
    // recurrent bias: added once (only kg==0 lanes seed accumulators with it)
    ULL rb[3];
#pragma unroll
    for (int g = 0; g < 3; g++) {
        float2 bv = *(const float2*)(rbias + g * 128 + 2 * q);
        rb[g] = (kg == 0) ? pack2(bv.x, bv.y) : 0ull;
    }

    // zero h buffer 0 (read at step 0)
    hp[0][t >> 7][t & 127] = 0ull;
    float2 hprev[2] = {make_float2(0.f, 0.f), make_float2(0.f, 0.f)};
    __syncthreads();

    for (int step = 0; step < TT; ++step) {
        const int rbuf = step & 1;
        const ULL (*hr)[UU] = hp[rbuf];
        ULL (*hw)[UU] = hp[rbuf ^ 1];

        // prefetch xw for this step (consumed after mainloop -> latency hidden)
        float2 xg[3][2];
#pragma unroll
        for (int g = 0; g < 3; g++) {
#pragma unroll
            for (int r = 0; r < 2; r++) {
                xg[g][r] = *(const float2*)(xw +
                    ((size_t)(row0 + r) * TT + step) * G3 + g * 128 + 2 * q);
            }
        }

        ULL acc[3][2];
#pragma unroll
        for (int g = 0; g < 3; g++) { acc[g][0] = rb[g]; acc[g][1] = rb[g]; }

        const ulonglong2* h0p = (const ulonglong2*)&hr[0][kbase];
        const ulonglong2* h1p = (const ulonglong2*)&hr[1][kbase];
#pragma unroll
        for (int j = 0; j < 16; j++) {
            ulonglong2 ha = h0p[j];   // (h,h) for k=2j, 2j+1, row0 (broadcast)
            ulonglong2 hb = h1p[j];   // row1
#pragma unroll
            for (int g = 0; g < 3; g++) {
                acc[g][0] = fma2(Ur[2 * j][g],     ha.x, acc[g][0]);
                acc[g][0] = fma2(Ur[2 * j + 1][g], ha.y, acc[g][0]);
                acc[g][1] = fma2(Ur[2 * j][g],     hb.x, acc[g][1]);
                acc[g][1] = fma2(Ur[2 * j + 1][g], hb.y, acc[g][1]);
            }
        }

        // kg-reduction: butterfly over lanes xor 8, xor 16 (all lanes end with full sum)
#pragma unroll
        for (int g = 0; g < 3; g++) {
#pragma unroll
            for (int r = 0; r < 2; r++)
                acc[g][r] = addp(acc[g][r], __shfl_xor_sync(0xffffffffu, acc[g][r], 8));
        }
#pragma unroll
        for (int g = 0; g < 3; g++) {
#pragma unroll
            for (int r = 0; r < 2; r++)
                acc[g][r] = addp(acc[g][r], __shfl_xor_sync(0xffffffffu, acc[g][r], 16));
        }

        // gates (all lanes compute redundantly; kg==0 lanes store)
#pragma unroll
        for (int r = 0; r < 2; r++) {
            float2 az = unpack2(acc[0][r]);
            float2 ar = unpack2(acc[1][r]);
            float2 ah = unpack2(acc[2][r]);
            float z0 = sigm(xg[0][r].x + az.x);
            float z1 = sigm(xg[0][r].y + az.y);
            float r0 = sigm(xg[1][r].x + ar.x);
            float r1 = sigm(xg[1][r].y + ar.y);
            float hh0 = fmaxf(xg[2][r].x + r0 * ah.x, 0.0f);
            float hh1 = fmaxf(xg[2][r].y + r1 * ah.y, 0.0f);
            float hn0 = z0 * hprev[r].x + (1.0f - z0) * hh0;
            float hn1 = z1 * hprev[r].y + (1.0f - z1) * hh1;
            hprev[r] = make_float2(hn0, hn1);
            if (kg == 0) {
                *(ulonglong2*)&hw[r][2 * q] =
                    make_ulonglong2(pack2(hn0, hn0), pack2(hn1, hn1));
                if (seqout)
                    seqout[((size_t)(row0 + r) * TT + step) * 64 + q] =
                        make_float2(hn0, hn1);
            }
        }
        __syncthreads();
    }

    if (kg == 0) {
#pragma unroll
        for (int r = 0; r < 2; r++) {
            hfin1[(size_t)(row0 + r) * 64 + q] = hprev[r];
            if (hfin2) hfin2[(size_t)(row0 + r) * 64 + q] = hprev[r];
        }
    }
}

// =====================================================================
// launch
// =====================================================================
extern "C" void kernel_launch(void* const* d_in, const int* in_sizes, int n_in,
                              void* d_out, int out_size)
{
    (void)in_sizes; (void)n_in; (void)out_size;
    const float* input = (const float*)d_in[0];  // [256,1024,64]
    const float* W1    = (const float*)d_in[1];  // [64,384]
    const float* U1    = (const float*)d_in[2];  // [128,384]
    const float* b1    = (const float*)d_in[3];  // [2,384]
    const float* W2    = (const float*)d_in[4];  // [128,384]
    const float* U2    = (const float*)d_in[5];  // [128,384]
    const float* b2    = (const float*)d_in[6];  // [2,384]
    float* out = (float*)d_out;                  // [3*256*128]: x | state1 | state2

    float *xw1, *seq1, *xw2;
    cudaGetSymbolAddress((void**)&xw1,  g_xw1);
    cudaGetSymbolAddress((void**)&seq1, g_seq1);
    cudaGetSymbolAddress((void**)&xw2,  g_xw2);

    const int SMEM_G1 = 64 * 1536 + 24576 + 2048;    // 124928
    const int SMEM_G2 = 128 * 1536 + 24576 + 4096;   // 225280

    cudaFuncSetAttribute(gemm_kernel<16>, cudaFuncAttributeMaxDynamicSharedMemorySize, SMEM_G1);
    cudaFuncSetAttribute(gemm_kernel<32>, cudaFuncAttributeMaxDynamicSharedMemorySize, SMEM_G2);

    const int nblk = (BB * TT) / 4;  // 65536 row-blocks of 4

    // Layer 1 input projection: xw1 = input @ W1 + b1[0]
    gemm_kernel<16><<<148, 384, SMEM_G1>>>(input, W1, b1, xw1, nblk);
    // Layer 1 scan: seq1, state1
    scan_kernel<<<128, 256>>>(xw1, U1, b1 + G3,
                              (float2*)seq1,
                              (float2*)(out + 32768), nullptr);
    // Layer 2 input projection: xw2 = seq1 @ W2 + b2[0]
    gemm_kernel<32><<<148, 384, SMEM_G2>>>(seq1, W2, b2, xw2, nblk);
    // Layer 2 scan: x (== state2)
    scan_kernel<<<128, 256>>>(xw2, U2, b2 + G3,
                              nullptr,
                              (float2*)out, (float2*)(out + 65536));
}